// round 9
// baseline (speedup 1.0000x reference)
#include <cuda_runtime.h>

// LIF neuron scan, T=16:
//   u1 = mem*0.5 + x[t]*0.5 ; spike = (u1 > 1) ; mem = spike ? 0 : u1
// HBM-roofline streaming kernel, 512 MB compulsory 1:1 R/W traffic.
//
// Operating point from R1-R8 (every lever isolated):
//   - 1 float4 column per thread, interleaved t-loop, pointer-bump
//     addressing, exact grid 4096x256, regs 32, occ ~86%
//     -> best isolated profile: 6434 GB/s, DRAM 81.2% (R8)
// R9 change: __stcs on STORES only (loads default). Hypothesis: default
// write-back leaves ~30MB of dirty output in L2 at kernel end; under
// back-to-back graph replay those writebacks drain into the next replay's
// read ramp (wall 84.0 vs ncu 75.4). Evict-first stores drain eagerly
// in-kernel -> cleaner replay boundary. (R2, the only prior .cs-store
// kernel, had the best wall time of the session despite a worse profile.)

#define TSTEPS 16

__global__ void __launch_bounds__(256)
lif_scan_kernel(const float* __restrict__ x, float* __restrict__ out)
{
    const unsigned col = blockIdx.x * 256u + threadIdx.x;   // 0 .. 2^20-1
    const unsigned stride4 = 1u << 20;                      // float4 cols per timestep

    const float4* __restrict__ xp = reinterpret_cast<const float4*>(x) + col;
    float4* __restrict__ op = reinterpret_cast<float4*>(out) + col;

    float4 mem = make_float4(0.f, 0.f, 0.f, 0.f);

    #pragma unroll
    for (int t = 0; t < TSTEPS; ++t) {
        const float4 xt = *xp;            // default policy (best: R2/R6 evidence)

        float4 s;
        float u;
        u = fmaf(mem.x, 0.5f, xt.x * 0.5f); s.x = (u > 1.f) ? 1.f : 0.f; mem.x = (u > 1.f) ? 0.f : u;
        u = fmaf(mem.y, 0.5f, xt.y * 0.5f); s.y = (u > 1.f) ? 1.f : 0.f; mem.y = (u > 1.f) ? 0.f : u;
        u = fmaf(mem.z, 0.5f, xt.z * 0.5f); s.z = (u > 1.f) ? 1.f : 0.f; mem.z = (u > 1.f) ? 0.f : u;
        u = fmaf(mem.w, 0.5f, xt.w * 0.5f); s.w = (u > 1.f) ? 1.f : 0.f; mem.w = (u > 1.f) ? 0.f : u;

        __stcs(op, s);                    // evict-first store: drain eagerly

        xp += stride4;
        op += stride4;
    }
}

extern "C" void kernel_launch(void* const* d_in, const int* in_sizes, int n_in,
                              void* d_out, int out_size)
{
    const float* x = (const float*)d_in[0];
    float* out = (float*)d_out;

    // 67,108,864 elements / 16 timesteps / 4 per float4 / 256 threads = 4096 CTAs exactly.
    lif_scan_kernel<<<4096, 256>>>(x, out);
}